// round 6
// baseline (speedup 1.0000x reference)
#include <cuda_runtime.h>

// ---------------------------------------------------------------------------
// NeuralODESIR R5: fused RK4 + 4-layer tanh MLP, fp32.
// 128 rows/CTA, 512 threads (16 warps/SM, 4/SMSP), 1 CTA/SM, weights in smem.
// f32x2-packed FMA microkernels; weights via broadcast LDS (~0.3 B/MAC).
// ---------------------------------------------------------------------------

typedef unsigned long long ull;

__device__ __forceinline__ ull fma2v(ull a, ull b, ull c) {
    ull d;
    asm("fma.rn.f32x2 %0, %1, %2, %3;" : "=l"(d) : "l"(a), "l"(b), "l"(c));
    return d;
}
__device__ __forceinline__ ull dup2(float x) {
    ull r;
    asm("mov.b64 %0, {%1, %1};" : "=l"(r) : "f"(x));
    return r;
}
__device__ __forceinline__ void unpack2(ull v, float& lo, float& hi) {
    asm("mov.b64 {%0, %1}, %2;" : "=f"(lo), "=f"(hi) : "l"(v));
}

// tanh(x) = 1 - 2/(exp(2x)+1); __expf ~2ulp, correct at +-large x.
__device__ __forceinline__ float tanh_fast(float x) {
    float e = __expf(2.0f * x);
    return 1.0f - __fdividef(2.0f, e + 1.0f);
}

// smem plan (floats)
#define OFF_W1   0
#define OFF_B1   (OFF_W1 + 320)
#define OFF_W2   (OFF_B1 + 64)
#define OFF_B2   (OFF_W2 + 8192)
#define OFF_W3   (OFF_B2 + 128)
#define OFF_B3   (OFF_W3 + 8192)
#define OFF_W4   (OFF_B3 + 64)
#define OFF_B4   (OFF_W4 + 192)
#define OFF_TS   (OFF_B4 + 4)
#define OFF_YIN  (OFF_TS + 128)
#define OFF_BUFA (OFF_YIN + 640)            // [64 feats][128 rows]
#define OFF_BUFB (OFF_BUFA + 64 * 128)      // [128 feats][128 rows]
#define SM_FLOATS (OFF_BUFB + 128 * 128)    // 42500 floats = 170000 B

__global__ void __launch_bounds__(512, 1)
node_sir_kernel(const float* __restrict__ y0, const float* __restrict__ t_span,
                const float* __restrict__ beta, const float* __restrict__ gamma_,
                const float* __restrict__ W1, const float* __restrict__ b1,
                const float* __restrict__ W2, const float* __restrict__ b2,
                const float* __restrict__ W3, const float* __restrict__ b3,
                const float* __restrict__ W4, const float* __restrict__ b4,
                float* __restrict__ out, int B, int T) {
    extern __shared__ float sm[];
    float* W1s  = sm + OFF_W1;
    float* b1s  = sm + OFF_B1;
    float* W2s  = sm + OFF_W2;
    float* b2s  = sm + OFF_B2;
    float* W3s  = sm + OFF_W3;
    float* b3s  = sm + OFF_B3;
    float* W4s  = sm + OFF_W4;
    float* b4s  = sm + OFF_B4;
    float* tss  = sm + OFF_TS;
    float* yin  = sm + OFF_YIN;   // [5][128]
    float* bufA = sm + OFF_BUFA;  // [64][128]
    float* bufB = sm + OFF_BUFB;  // [128][128]

    const int t    = threadIdx.x;
    const int lane = t & 31;
    const int warp = t >> 5;

    for (int i = t; i < 320; i += 512) W1s[i] = W1[i];
    if (t < 64) b1s[t] = b1[t];
    for (int i = t; i < 8192; i += 512) W2s[i] = W2[i];
    if (t < 128) b2s[t] = b2[t];
    for (int i = t; i < 8192; i += 512) W3s[i] = W3[i];
    if (t < 64) b3s[t] = b3[t];
    if (t < 192) W4s[t] = W4[t];
    if (t < 3) b4s[t] = b4[t];
    if (t < T && t < 128) tss[t] = t_span[t];

    const int b0   = blockIdx.x << 7;
    const int row4 = t >> 2;   // layer-4 / state: one row per 4 threads
    const int part = t & 3;    // layer-4 split-K quarter

    float bS = 0.f, bI = 0.f, bR = 0.f;
    float aS = 0.f, aI = 0.f, aR = 0.f;

    if (part == 0) {
        int gr = b0 + row4;
        bS = y0[gr * 3 + 0];
        bI = y0[gr * 3 + 1];
        bR = y0[gr * 3 + 2];
        yin[row4]        = bS;
        yin[128 + row4]  = bI;
        yin[256 + row4]  = bR;
        yin[384 + row4]  = beta[gr];
        yin[512 + row4]  = gamma_[gr];
        float m  = fmaxf(bS, fmaxf(bI, bR));
        float e0 = __expf(bS - m), e1 = __expf(bI - m), e2 = __expf(bR - m);
        float inv = __fdividef(1.0f, e0 + e1 + e2);
        size_t o = (size_t)gr * 3;
        out[o] = e0 * inv; out[o + 1] = e1 * inv; out[o + 2] = e2 * inv;
    }
    __syncthreads();

    const int c0_2 = warp << 3;   // layer-2: 8 cols per warp  (N=128, 16 warps)
    const int c0_3 = warp << 2;   // layer-3: 4 cols per warp  (N=64,  16 warps)
    const int r4   = lane << 2;   // 4 rows per lane

    for (int s = 0; s < T - 1; ++s) {
        float dt = tss[s + 1] - tss[s];
        for (int sub = 0; sub < 4; ++sub) {
            // ---------- Layer 1: [128,5] @ [5,64] -> bufA[64][128] ----------
            {
                const int r  = t & 127;
                const int cb = (t >> 7) << 4;   // 16 cols per thread
                float v0 = yin[r],       v1 = yin[128 + r], v2 = yin[256 + r];
                float v3 = yin[384 + r], v4 = yin[512 + r];
#pragma unroll 4
                for (int j = 0; j < 16; ++j) {
                    int c = cb + j;
                    float v = b1s[c];
                    v = fmaf(v0, W1s[c],        v);
                    v = fmaf(v1, W1s[64 + c],   v);
                    v = fmaf(v2, W1s[128 + c],  v);
                    v = fmaf(v3, W1s[192 + c],  v);
                    v = fmaf(v4, W1s[256 + c],  v);
                    bufA[(c << 7) + r] = tanh_fast(v);
                }
            }
            __syncthreads();

            // ---------- Layer 2: K=64 -> N=128, bufA -> bufB ----------
            {
                ull acc[4][4];
#pragma unroll
                for (int jp = 0; jp < 4; ++jp) {
                    ull bb = *reinterpret_cast<const ull*>(b2s + c0_2 + 2 * jp);
                    acc[0][jp] = bb; acc[1][jp] = bb; acc[2][jp] = bb; acc[3][jp] = bb;
                }
#pragma unroll 4
                for (int k = 0; k < 64; ++k) {
                    float4 a = *reinterpret_cast<const float4*>(bufA + (k << 7) + r4);
                    ull ad0 = dup2(a.x), ad1 = dup2(a.y), ad2 = dup2(a.z), ad3 = dup2(a.w);
                    const ulonglong2* wp =
                        reinterpret_cast<const ulonglong2*>(W2s + (k << 7) + c0_2);
                    ulonglong2 wv0 = wp[0], wv1 = wp[1];
                    ull w[4] = {wv0.x, wv0.y, wv1.x, wv1.y};
#pragma unroll
                    for (int jp = 0; jp < 4; ++jp) {
                        acc[0][jp] = fma2v(ad0, w[jp], acc[0][jp]);
                        acc[1][jp] = fma2v(ad1, w[jp], acc[1][jp]);
                        acc[2][jp] = fma2v(ad2, w[jp], acc[2][jp]);
                        acc[3][jp] = fma2v(ad3, w[jp], acc[3][jp]);
                    }
                }
#pragma unroll
                for (int jp = 0; jp < 4; ++jp) {
                    float x0l, x0h, x1l, x1h, x2l, x2h, x3l, x3h;
                    unpack2(acc[0][jp], x0l, x0h);
                    unpack2(acc[1][jp], x1l, x1h);
                    unpack2(acc[2][jp], x2l, x2h);
                    unpack2(acc[3][jp], x3l, x3h);
                    int c = c0_2 + 2 * jp;
                    *reinterpret_cast<float4*>(bufB + (c << 7) + r4) =
                        make_float4(tanh_fast(x0l), tanh_fast(x1l),
                                    tanh_fast(x2l), tanh_fast(x3l));
                    *reinterpret_cast<float4*>(bufB + ((c + 1) << 7) + r4) =
                        make_float4(tanh_fast(x0h), tanh_fast(x1h),
                                    tanh_fast(x2h), tanh_fast(x3h));
                }
            }
            __syncthreads();

            // ---------- Layer 3: K=128 -> N=64, bufB -> bufA ----------
            {
                ull acc[4][2];
#pragma unroll
                for (int jp = 0; jp < 2; ++jp) {
                    ull bb = *reinterpret_cast<const ull*>(b3s + c0_3 + 2 * jp);
                    acc[0][jp] = bb; acc[1][jp] = bb; acc[2][jp] = bb; acc[3][jp] = bb;
                }
#pragma unroll 4
                for (int k = 0; k < 128; ++k) {
                    float4 a = *reinterpret_cast<const float4*>(bufB + (k << 7) + r4);
                    ull ad0 = dup2(a.x), ad1 = dup2(a.y), ad2 = dup2(a.z), ad3 = dup2(a.w);
                    ulonglong2 wv =
                        *reinterpret_cast<const ulonglong2*>(W3s + (k << 6) + c0_3);
#pragma unroll
                    for (int jp = 0; jp < 2; ++jp) {
                        ull w = jp ? wv.y : wv.x;
                        acc[0][jp] = fma2v(ad0, w, acc[0][jp]);
                        acc[1][jp] = fma2v(ad1, w, acc[1][jp]);
                        acc[2][jp] = fma2v(ad2, w, acc[2][jp]);
                        acc[3][jp] = fma2v(ad3, w, acc[3][jp]);
                    }
                }
#pragma unroll
                for (int jp = 0; jp < 2; ++jp) {
                    float x0l, x0h, x1l, x1h, x2l, x2h, x3l, x3h;
                    unpack2(acc[0][jp], x0l, x0h);
                    unpack2(acc[1][jp], x1l, x1h);
                    unpack2(acc[2][jp], x2l, x2h);
                    unpack2(acc[3][jp], x3l, x3h);
                    int c = c0_3 + 2 * jp;
                    *reinterpret_cast<float4*>(bufA + (c << 7) + r4) =
                        make_float4(tanh_fast(x0l), tanh_fast(x1l),
                                    tanh_fast(x2l), tanh_fast(x3l));
                    *reinterpret_cast<float4*>(bufA + ((c + 1) << 7) + r4) =
                        make_float4(tanh_fast(x0h), tanh_fast(x1h),
                                    tanh_fast(x2h), tanh_fast(x3h));
                }
            }
            __syncthreads();

            // ---------- Layer 4 (split-K over 4 threads/row) + RK4 ----------
            {
                float s0 = 0.f, s1 = 0.f, s2 = 0.f;
                const int kb = part << 4;
#pragma unroll
                for (int i = 0; i < 16; ++i) {
                    int k = kb + i;
                    float h = bufA[(k << 7) + row4];
                    s0 = fmaf(h, W4s[k * 3 + 0], s0);
                    s1 = fmaf(h, W4s[k * 3 + 1], s1);
                    s2 = fmaf(h, W4s[k * 3 + 2], s2);
                }
                s0 += __shfl_xor_sync(0xffffffffu, s0, 1);
                s1 += __shfl_xor_sync(0xffffffffu, s1, 1);
                s2 += __shfl_xor_sync(0xffffffffu, s2, 1);
                s0 += __shfl_xor_sync(0xffffffffu, s0, 2);
                s1 += __shfl_xor_sync(0xffffffffu, s1, 2);
                s2 += __shfl_xor_sync(0xffffffffu, s2, 2);

                if (part == 0) {
                    s0 += b4s[0]; s1 += b4s[1]; s2 += b4s[2];
                    if (sub == 0) {
                        aS = s0; aI = s1; aR = s2;
                    } else if (sub == 3) {
                        aS += s0; aI += s1; aR += s2;
                    } else {
                        aS = fmaf(2.0f, s0, aS);
                        aI = fmaf(2.0f, s1, aI);
                        aR = fmaf(2.0f, s2, aR);
                    }
                    if (sub < 3) {
                        float cy = (sub == 2) ? dt : 0.5f * dt;
                        yin[row4]        = fmaf(cy, s0, bS);
                        yin[128 + row4]  = fmaf(cy, s1, bI);
                        yin[256 + row4]  = fmaf(cy, s2, bR);
                    } else {
                        float c = dt * (1.0f / 6.0f);
                        bS = fmaf(c, aS, bS);
                        bI = fmaf(c, aI, bI);
                        bR = fmaf(c, aR, bR);
                        yin[row4]        = bS;
                        yin[128 + row4]  = bI;
                        yin[256 + row4]  = bR;
                        float m  = fmaxf(bS, fmaxf(bI, bR));
                        float e0 = __expf(bS - m), e1 = __expf(bI - m), e2 = __expf(bR - m);
                        float inv = __fdividef(1.0f, e0 + e1 + e2);
                        size_t o = ((size_t)(s + 1) * B + (b0 + row4)) * 3;
                        out[o] = e0 * inv; out[o + 1] = e1 * inv; out[o + 2] = e2 * inv;
                    }
                }
            }
            __syncthreads();
        }
    }
}

extern "C" void kernel_launch(void* const* d_in, const int* in_sizes, int n_in,
                              void* d_out, int out_size) {
    const float* y0 = (const float*)d_in[0];
    const float* ts = (const float*)d_in[1];
    const float* be = (const float*)d_in[2];
    const float* ga = (const float*)d_in[3];
    const float* W1 = (const float*)d_in[4];
    const float* b1 = (const float*)d_in[5];
    const float* W2 = (const float*)d_in[6];
    const float* b2 = (const float*)d_in[7];
    const float* W3 = (const float*)d_in[8];
    const float* b3 = (const float*)d_in[9];
    const float* W4 = (const float*)d_in[10];
    const float* b4 = (const float*)d_in[11];

    int B = in_sizes[2];  // beta length
    int T = in_sizes[1];  // t_span length

    size_t smem_bytes = (size_t)SM_FLOATS * sizeof(float);
    cudaFuncSetAttribute(node_sir_kernel,
                         cudaFuncAttributeMaxDynamicSharedMemorySize,
                         (int)smem_bytes);

    node_sir_kernel<<<B / 128, 512, smem_bytes>>>(
        y0, ts, be, ga, W1, b1, W2, b2, W3, b3, W4, b4,
        (float*)d_out, B, T);
}

// round 8
// speedup vs baseline: 2.2336x; 2.2336x over previous
#include <cuda_runtime.h>
#include <cuda_fp16.h>

typedef unsigned int u32;

// ---------------------------------------------------------------------------
// NeuralODESIR R8: RK4 + 4-layer tanh MLP. L2/L3 GEMMs on HMMA via
// mma.sync.m16n8k16 (f16 inputs, f32 accum), fp16 2-way-split x 3 terms.
// Compiles from base compute_100 PTX (no tcgen05). 128 rows/CTA, 512 threads.
// ---------------------------------------------------------------------------

// ---- smem byte offsets ----
#define SB_W1    0          // fp32[320]
#define SB_B1    1280       // fp32[64]
#define SB_B2    1536       // fp32[128]
#define SB_B3    2048       // fp32[64]
#define SB_W4    2304       // fp32[192]
#define SB_B4    3072       // fp32[3]
#define SB_TS    3088       // fp32[128]
#define SB_YIN   3600       // fp32[5][128]
#define SB_RED   6160       // fp32[4][3][128]
#define SB_W2H   12416      // half[64][136]  (17408 B each)
#define SB_W2M   29824
#define SB_W3H   47232      // half[128][72]  (18432 B each)
#define SB_W3M   65664
#define SB_A2H   84096      // half[128][72]
#define SB_A2M   102528
#define SB_A3H   120960     // half[128][136] (34816 B each)
#define SB_A3M   155776
#define SB_TOTAL 190592

#define SA2 144   // A2 row stride bytes (72 halfs)
#define SA3 272   // A3 row stride bytes (136 halfs)
#define SW2 272   // W2 row stride bytes
#define SW3 144   // W3 row stride bytes

__device__ __forceinline__ u32 smem_u32(const void* p) {
    u32 a;
    asm("{ .reg .u64 t; cvta.to.shared.u64 t, %1; cvt.u32.u64 %0, t; }" : "=r"(a) : "l"(p));
    return a;
}
__device__ __forceinline__ void ldsm_x4(u32* r, u32 addr) {
    asm volatile("ldmatrix.sync.aligned.m8n8.x4.shared.b16 {%0,%1,%2,%3}, [%4];"
        : "=r"(r[0]), "=r"(r[1]), "=r"(r[2]), "=r"(r[3]) : "r"(addr));
}
__device__ __forceinline__ void ldsm_x4_t(u32* r, u32 addr) {
    asm volatile("ldmatrix.sync.aligned.m8n8.x4.trans.shared.b16 {%0,%1,%2,%3}, [%4];"
        : "=r"(r[0]), "=r"(r[1]), "=r"(r[2]), "=r"(r[3]) : "r"(addr));
}
__device__ __forceinline__ void mma16816(float* d, const u32* a, const u32* b) {
    asm volatile("mma.sync.aligned.m16n8k16.row.col.f32.f16.f16.f32 "
        "{%0,%1,%2,%3},{%4,%5,%6,%7},{%8,%9},{%0,%1,%2,%3};"
        : "+f"(d[0]), "+f"(d[1]), "+f"(d[2]), "+f"(d[3])
        : "r"(a[0]), "r"(a[1]), "r"(a[2]), "r"(a[3]), "r"(b[0]), "r"(b[1]));
}
__device__ __forceinline__ float tanh_fast(float x) {
    float e = __expf(2.0f * x);
    return 1.0f - __fdividef(2.0f, e + 1.0f);
}
// two fp32 -> packed fp16 high/residual halves
__device__ __forceinline__ void split2(float x0, float x1, u32& h, u32& m) {
    __half h0 = __float2half_rn(x0), h1 = __float2half_rn(x1);
    float r0 = x0 - __half2float(h0), r1 = x1 - __half2float(h1);
    __half m0 = __float2half_rn(r0), m1 = __float2half_rn(r1);
    __half2 hp = __halves2half2(h0, h1), mp = __halves2half2(m0, m1);
    h = *reinterpret_cast<u32*>(&hp);
    m = *reinterpret_cast<u32*>(&mp);
}

__global__ void __launch_bounds__(512, 1)
node_sir_mma(const float* __restrict__ y0, const float* __restrict__ t_span,
             const float* __restrict__ beta, const float* __restrict__ gamma_,
             const float* __restrict__ W1, const float* __restrict__ b1,
             const float* __restrict__ W2, const float* __restrict__ b2,
             const float* __restrict__ W3, const float* __restrict__ b3,
             const float* __restrict__ W4, const float* __restrict__ b4,
             float* __restrict__ out, int B, int T) {
    extern __shared__ char smem[];
    float* W1s = (float*)(smem + SB_W1);
    float* b1s = (float*)(smem + SB_B1);
    float* b2s = (float*)(smem + SB_B2);
    float* b3s = (float*)(smem + SB_B3);
    float* W4s = (float*)(smem + SB_W4);
    float* b4s = (float*)(smem + SB_B4);
    float* tss = (float*)(smem + SB_TS);
    float* yin = (float*)(smem + SB_YIN);
    float* red = (float*)(smem + SB_RED);

    const u32 sbase = smem_u32(smem);
    const int t = threadIdx.x, lane = t & 31, w = t >> 5;

    // small fp32 params
    for (int i = t; i < 320; i += 512) W1s[i] = W1[i];
    if (t < 64)  b1s[t] = b1[t];
    if (t < 128) b2s[t] = b2[t];
    if (t < 64)  b3s[t] = b3[t];
    if (t < 192) W4s[t] = W4[t];
    if (t < 3)   b4s[t] = b4[t];
    if (t < T && t < 128) tss[t] = t_span[t];

    // split weights to fp16 h/m (stored [K][N_pad], row-major)
    for (int idx = t; idx < 8192; idx += 512) {   // W2 [64][128]
        int k = idx >> 7, n = idx & 127;
        float v = W2[idx];
        __half h = __float2half_rn(v);
        __half m = __float2half_rn(v - __half2float(h));
        int off = k * 136 + n;
        *(__half*)(smem + SB_W2H + off * 2) = h;
        *(__half*)(smem + SB_W2M + off * 2) = m;
    }
    for (int idx = t; idx < 8192; idx += 512) {   // W3 [128][64]
        int k = idx >> 6, n = idx & 63;
        float v = W3[idx];
        __half h = __float2half_rn(v);
        __half m = __float2half_rn(v - __half2float(h));
        int off = k * 72 + n;
        *(__half*)(smem + SB_W3H + off * 2) = h;
        *(__half*)(smem + SB_W3M + off * 2) = m;
    }

    const int b0 = blockIdx.x << 7;
    float bS = 0.f, bI = 0.f, bR = 0.f, aS = 0.f, aI = 0.f, aR = 0.f;
    if (t < 128) {
        int gr = b0 + t;
        bS = y0[gr * 3 + 0]; bI = y0[gr * 3 + 1]; bR = y0[gr * 3 + 2];
        yin[t] = bS; yin[128 + t] = bI; yin[256 + t] = bR;
        yin[384 + t] = beta[gr]; yin[512 + t] = gamma_[gr];
        float mx = fmaxf(bS, fmaxf(bI, bR));
        float e0 = __expf(bS - mx), e1 = __expf(bI - mx), e2 = __expf(bR - mx);
        float inv = __fdividef(1.0f, e0 + e1 + e2);
        size_t o = (size_t)gr * 3;
        out[o] = e0 * inv; out[o + 1] = e1 * inv; out[o + 2] = e2 * inv;
    }
    __syncthreads();

    // warp tiling
    const int wm = w & 3, wn = w >> 2;
    const int m0 = wm << 5;        // 32 rows per warp
    const int n2 = wn << 5;        // L2: 32 cols per warp (N=128)
    const int n3 = wn << 4;        // L3: 16 cols per warp (N=64)
    const int lr  = lane & 15;
    const int hi8 = (lane >> 4) << 3;
    const int g   = lane >> 2, tq = lane & 3;

    // per-lane ldmatrix byte offsets
    const u32 a2ro = (u32)((m0 + lr) * SA2 + hi8 * 2);
    const u32 b2ro = (u32)(lr * SW2 + (n2 + hi8) * 2);
    const u32 a3ro = (u32)((m0 + lr) * SA3 + hi8 * 2);
    const u32 b3ro = (u32)(lr * SW3 + (n3 + hi8) * 2);

    const int r1row = t & 127;            // layer-1 row
    const int cb    = (t >> 7) << 4;      // layer-1 feature base (16 feats)

    for (int s = 0; s < T - 1; ++s) {
        float dt = tss[s + 1] - tss[s];
        for (int sub = 0; sub < 4; ++sub) {
            // ---- Layer 1 (fp32) -> split -> A2 h/m ----
            {
                float yv0 = yin[r1row],        yv1 = yin[128 + r1row];
                float yv2 = yin[256 + r1row],  yv3 = yin[384 + r1row];
                float yv4 = yin[512 + r1row];
                int rb = r1row * SA2;
#pragma unroll
                for (int j = 0; j < 16; j += 2) {
                    int c = cb + j;
                    float v0 = b1s[c], v1 = b1s[c + 1];
                    v0 = fmaf(yv0, W1s[c],        v0); v1 = fmaf(yv0, W1s[c + 1],        v1);
                    v0 = fmaf(yv1, W1s[64 + c],   v0); v1 = fmaf(yv1, W1s[64 + c + 1],   v1);
                    v0 = fmaf(yv2, W1s[128 + c],  v0); v1 = fmaf(yv2, W1s[128 + c + 1],  v1);
                    v0 = fmaf(yv3, W1s[192 + c],  v0); v1 = fmaf(yv3, W1s[192 + c + 1],  v1);
                    v0 = fmaf(yv4, W1s[256 + c],  v0); v1 = fmaf(yv4, W1s[256 + c + 1],  v1);
                    u32 hp, mp;
                    split2(tanh_fast(v0), tanh_fast(v1), hp, mp);
                    *(u32*)(smem + SB_A2H + rb + c * 2) = hp;
                    *(u32*)(smem + SB_A2M + rb + c * 2) = mp;
                }
            }
            __syncthreads();

            // ---- L2 GEMM: D2[128][128], K=64 x 3 terms ----
            float acc2[2][4][4];
#pragma unroll
            for (int i = 0; i < 2; ++i)
#pragma unroll
                for (int j = 0; j < 4; ++j)
#pragma unroll
                    for (int c = 0; c < 4; ++c) acc2[i][j][c] = 0.f;
#pragma unroll
            for (int tm = 0; tm < 3; ++tm) {
                u32 Ab = sbase + (tm < 2 ? SB_A2H : SB_A2M);
                u32 Wb = sbase + (tm == 1 ? SB_W2M : SB_W2H);
#pragma unroll
                for (int kc = 0; kc < 4; ++kc) {
                    u32 af0[4], af1[4], bf0[4], bf1[4];
                    ldsm_x4(af0, Ab + a2ro + (u32)(kc << 5));
                    ldsm_x4(af1, Ab + a2ro + (u32)(16 * SA2) + (u32)(kc << 5));
                    ldsm_x4_t(bf0, Wb + b2ro + (u32)(kc * 16 * SW2));
                    ldsm_x4_t(bf1, Wb + b2ro + (u32)(kc * 16 * SW2) + 32u);
                    mma16816(acc2[0][0], af0, bf0);
                    mma16816(acc2[0][1], af0, bf0 + 2);
                    mma16816(acc2[0][2], af0, bf1);
                    mma16816(acc2[0][3], af0, bf1 + 2);
                    mma16816(acc2[1][0], af1, bf0);
                    mma16816(acc2[1][1], af1, bf0 + 2);
                    mma16816(acc2[1][2], af1, bf1);
                    mma16816(acc2[1][3], af1, bf1 + 2);
                }
            }
            // ---- epi2: +b2, tanh, split -> A3 h/m ----
#pragma unroll
            for (int mt = 0; mt < 2; ++mt) {
                int rlo = m0 + (mt << 4) + g;
#pragma unroll
                for (int nt = 0; nt < 4; ++nt) {
                    int cc = n2 + (nt << 3) + (tq << 1);
                    float bb0 = b2s[cc], bb1 = b2s[cc + 1];
                    u32 hp, mp;
                    split2(tanh_fast(acc2[mt][nt][0] + bb0),
                           tanh_fast(acc2[mt][nt][1] + bb1), hp, mp);
                    *(u32*)(smem + SB_A3H + rlo * SA3 + cc * 2) = hp;
                    *(u32*)(smem + SB_A3M + rlo * SA3 + cc * 2) = mp;
                    split2(tanh_fast(acc2[mt][nt][2] + bb0),
                           tanh_fast(acc2[mt][nt][3] + bb1), hp, mp);
                    *(u32*)(smem + SB_A3H + (rlo + 8) * SA3 + cc * 2) = hp;
                    *(u32*)(smem + SB_A3M + (rlo + 8) * SA3 + cc * 2) = mp;
                }
            }
            __syncthreads();

            // ---- L3 GEMM: D3[128][64], K=128 x 3 terms ----
            float acc3[2][2][4];
#pragma unroll
            for (int i = 0; i < 2; ++i)
#pragma unroll
                for (int j = 0; j < 2; ++j)
#pragma unroll
                    for (int c = 0; c < 4; ++c) acc3[i][j][c] = 0.f;
#pragma unroll
            for (int tm = 0; tm < 3; ++tm) {
                u32 Ab = sbase + (tm < 2 ? SB_A3H : SB_A3M);
                u32 Wb = sbase + (tm == 1 ? SB_W3M : SB_W3H);
#pragma unroll
                for (int kc = 0; kc < 8; ++kc) {
                    u32 af0[4], af1[4], bf[4];
                    ldsm_x4(af0, Ab + a3ro + (u32)(kc << 5));
                    ldsm_x4(af1, Ab + a3ro + (u32)(16 * SA3) + (u32)(kc << 5));
                    ldsm_x4_t(bf, Wb + b3ro + (u32)(kc * 16 * SW3));
                    mma16816(acc3[0][0], af0, bf);
                    mma16816(acc3[0][1], af0, bf + 2);
                    mma16816(acc3[1][0], af1, bf);
                    mma16816(acc3[1][1], af1, bf + 2);
                }
            }
            // ---- epi3: +b3, tanh, W4 partial dot, reduce ----
#pragma unroll
            for (int mt = 0; mt < 2; ++mt) {
#pragma unroll
                for (int p = 0; p < 2; ++p) {
                    int row = m0 + (mt << 4) + g + (p << 3);
                    float s0 = 0.f, s1 = 0.f, s2 = 0.f;
#pragma unroll
                    for (int nt = 0; nt < 2; ++nt) {
                        int cc = n3 + (nt << 3) + (tq << 1);
                        float h0 = tanh_fast(acc3[mt][nt][p ? 2 : 0] + b3s[cc]);
                        float h1 = tanh_fast(acc3[mt][nt][p ? 3 : 1] + b3s[cc + 1]);
                        s0 = fmaf(h0, W4s[cc * 3 + 0], s0); s0 = fmaf(h1, W4s[cc * 3 + 3], s0);
                        s1 = fmaf(h0, W4s[cc * 3 + 1], s1); s1 = fmaf(h1, W4s[cc * 3 + 4], s1);
                        s2 = fmaf(h0, W4s[cc * 3 + 2], s2); s2 = fmaf(h1, W4s[cc * 3 + 5], s2);
                    }
                    s0 += __shfl_xor_sync(0xffffffffu, s0, 1);
                    s1 += __shfl_xor_sync(0xffffffffu, s1, 1);
                    s2 += __shfl_xor_sync(0xffffffffu, s2, 1);
                    s0 += __shfl_xor_sync(0xffffffffu, s0, 2);
                    s1 += __shfl_xor_sync(0xffffffffu, s1, 2);
                    s2 += __shfl_xor_sync(0xffffffffu, s2, 2);
                    if (tq == 0) {
                        red[wn * 384 + row]        = s0;
                        red[wn * 384 + 128 + row]  = s1;
                        red[wn * 384 + 256 + row]  = s2;
                    }
                }
            }
            __syncthreads();

            // ---- RK4 + output (threads 0..127) ----
            if (t < 128) {
                float s0 = b4s[0] + red[t]        + red[384 + t]
                                  + red[768 + t]  + red[1152 + t];
                float s1 = b4s[1] + red[128 + t]  + red[512 + t]
                                  + red[896 + t]  + red[1280 + t];
                float s2 = b4s[2] + red[256 + t]  + red[640 + t]
                                  + red[1024 + t] + red[1408 + t];
                if (sub == 0)      { aS = s0; aI = s1; aR = s2; }
                else if (sub == 3) { aS += s0; aI += s1; aR += s2; }
                else {
                    aS = fmaf(2.0f, s0, aS); aI = fmaf(2.0f, s1, aI); aR = fmaf(2.0f, s2, aR);
                }
                if (sub < 3) {
                    float cy = (sub == 2) ? dt : 0.5f * dt;
                    yin[t]       = fmaf(cy, s0, bS);
                    yin[128 + t] = fmaf(cy, s1, bI);
                    yin[256 + t] = fmaf(cy, s2, bR);
                } else {
                    float cc = dt * (1.0f / 6.0f);
                    bS = fmaf(cc, aS, bS); bI = fmaf(cc, aI, bI); bR = fmaf(cc, aR, bR);
                    yin[t] = bS; yin[128 + t] = bI; yin[256 + t] = bR;
                    float mx = fmaxf(bS, fmaxf(bI, bR));
                    float e0 = __expf(bS - mx), e1 = __expf(bI - mx), e2 = __expf(bR - mx);
                    float inv = __fdividef(1.0f, e0 + e1 + e2);
                    size_t o = ((size_t)(s + 1) * B + (b0 + t)) * 3;
                    out[o] = e0 * inv; out[o + 1] = e1 * inv; out[o + 2] = e2 * inv;
                }
            }
            __syncthreads();
        }
    }
}

extern "C" void kernel_launch(void* const* d_in, const int* in_sizes, int n_in,
                              void* d_out, int out_size) {
    const float* y0 = (const float*)d_in[0];
    const float* ts = (const float*)d_in[1];
    const float* be = (const float*)d_in[2];
    const float* ga = (const float*)d_in[3];
    const float* W1 = (const float*)d_in[4];
    const float* b1 = (const float*)d_in[5];
    const float* W2 = (const float*)d_in[6];
    const float* b2 = (const float*)d_in[7];
    const float* W3 = (const float*)d_in[8];
    const float* b3 = (const float*)d_in[9];
    const float* W4 = (const float*)d_in[10];
    const float* b4 = (const float*)d_in[11];

    int B = in_sizes[2];
    int T = in_sizes[1];

    cudaFuncSetAttribute(node_sir_mma, cudaFuncAttributeMaxDynamicSharedMemorySize, SB_TOTAL);
    node_sir_mma<<<B / 128, 512, SB_TOTAL>>>(
        y0, ts, be, ga, W1, b1, W2, b2, W3, b3, W4, b4, (float*)d_out, B, T);
}

// round 10
// speedup vs baseline: 2.3649x; 1.0588x over previous
#include <cuda_runtime.h>
#include <cuda_fp16.h>

typedef unsigned int u32;

// ---------------------------------------------------------------------------
// NeuralODESIR R10 (retry of R9): RK4 + 4-layer tanh MLP. L2/L3 GEMMs on HMMA
// (mma.sync.m16n8k16, f16 in / f32 accum), fp16 2-way-split x 3 terms.
// R8 + fragment reuse: Ah/Am/Wh loaded once per k-chunk (-33% ldmatrix).
// ---------------------------------------------------------------------------

// ---- smem byte offsets ----
#define SB_W1    0          // fp32[320]
#define SB_B1    1280       // fp32[64]
#define SB_B2    1536       // fp32[128]
#define SB_B3    2048       // fp32[64]
#define SB_W4    2304       // fp32[192]
#define SB_B4    3072       // fp32[3]
#define SB_TS    3088       // fp32[128]
#define SB_YIN   3600       // fp32[5][128]
#define SB_RED   6160       // fp32[4][3][128]
#define SB_W2H   12416      // half[64][136]
#define SB_W2M   29824
#define SB_W3H   47232      // half[128][72]
#define SB_W3M   65664
#define SB_A2H   84096      // half[128][72]
#define SB_A2M   102528
#define SB_A3H   120960     // half[128][136]
#define SB_A3M   155776
#define SB_TOTAL 190592

#define SA2 144   // A2 row stride bytes
#define SA3 272   // A3 row stride bytes
#define SW2 272   // W2 row stride bytes
#define SW3 144   // W3 row stride bytes

__device__ __forceinline__ u32 smem_u32(const void* p) {
    u32 a;
    asm("{ .reg .u64 t; cvta.to.shared.u64 t, %1; cvt.u32.u64 %0, t; }" : "=r"(a) : "l"(p));
    return a;
}
__device__ __forceinline__ void ldsm_x4(u32* r, u32 addr) {
    asm volatile("ldmatrix.sync.aligned.m8n8.x4.shared.b16 {%0,%1,%2,%3}, [%4];"
        : "=r"(r[0]), "=r"(r[1]), "=r"(r[2]), "=r"(r[3]) : "r"(addr));
}
__device__ __forceinline__ void ldsm_x4_t(u32* r, u32 addr) {
    asm volatile("ldmatrix.sync.aligned.m8n8.x4.trans.shared.b16 {%0,%1,%2,%3}, [%4];"
        : "=r"(r[0]), "=r"(r[1]), "=r"(r[2]), "=r"(r[3]) : "r"(addr));
}
__device__ __forceinline__ void mma16816(float* d, const u32* a, const u32* b) {
    asm volatile("mma.sync.aligned.m16n8k16.row.col.f32.f16.f16.f32 "
        "{%0,%1,%2,%3},{%4,%5,%6,%7},{%8,%9},{%0,%1,%2,%3};"
        : "+f"(d[0]), "+f"(d[1]), "+f"(d[2]), "+f"(d[3])
        : "r"(a[0]), "r"(a[1]), "r"(a[2]), "r"(a[3]), "r"(b[0]), "r"(b[1]));
}
__device__ __forceinline__ float tanh_fast(float x) {
    float e = __expf(2.0f * x);
    return 1.0f - __fdividef(2.0f, e + 1.0f);
}
__device__ __forceinline__ void split2(float x0, float x1, u32& h, u32& m) {
    __half h0 = __float2half_rn(x0), h1 = __float2half_rn(x1);
    float r0 = x0 - __half2float(h0), r1 = x1 - __half2float(h1);
    __half m0 = __float2half_rn(r0), m1 = __float2half_rn(r1);
    __half2 hp = __halves2half2(h0, h1), mp = __halves2half2(m0, m1);
    h = *reinterpret_cast<u32*>(&hp);
    m = *reinterpret_cast<u32*>(&mp);
}

__global__ void __launch_bounds__(512, 1)
node_sir_mma(const float* __restrict__ y0, const float* __restrict__ t_span,
             const float* __restrict__ beta, const float* __restrict__ gamma_,
             const float* __restrict__ W1, const float* __restrict__ b1,
             const float* __restrict__ W2, const float* __restrict__ b2,
             const float* __restrict__ W3, const float* __restrict__ b3,
             const float* __restrict__ W4, const float* __restrict__ b4,
             float* __restrict__ out, int B, int T) {
    extern __shared__ char smem[];
    float* W1s = (float*)(smem + SB_W1);
    float* b1s = (float*)(smem + SB_B1);
    float* b2s = (float*)(smem + SB_B2);
    float* b3s = (float*)(smem + SB_B3);
    float* W4s = (float*)(smem + SB_W4);
    float* b4s = (float*)(smem + SB_B4);
    float* tss = (float*)(smem + SB_TS);
    float* yin = (float*)(smem + SB_YIN);
    float* red = (float*)(smem + SB_RED);

    const u32 sbase = smem_u32(smem);
    const int t = threadIdx.x, lane = t & 31, w = t >> 5;

    for (int i = t; i < 320; i += 512) W1s[i] = W1[i];
    if (t < 64)  b1s[t] = b1[t];
    if (t < 128) b2s[t] = b2[t];
    if (t < 64)  b3s[t] = b3[t];
    if (t < 192) W4s[t] = W4[t];
    if (t < 3)   b4s[t] = b4[t];
    if (t < T && t < 128) tss[t] = t_span[t];

    for (int idx = t; idx < 8192; idx += 512) {   // W2 [64][128]
        int k = idx >> 7, n = idx & 127;
        float v = W2[idx];
        __half h = __float2half_rn(v);
        __half m = __float2half_rn(v - __half2float(h));
        int off = k * 136 + n;
        *(__half*)(smem + SB_W2H + off * 2) = h;
        *(__half*)(smem + SB_W2M + off * 2) = m;
    }
    for (int idx = t; idx < 8192; idx += 512) {   // W3 [128][64]
        int k = idx >> 6, n = idx & 63;
        float v = W3[idx];
        __half h = __float2half_rn(v);
        __half m = __float2half_rn(v - __half2float(h));
        int off = k * 72 + n;
        *(__half*)(smem + SB_W3H + off * 2) = h;
        *(__half*)(smem + SB_W3M + off * 2) = m;
    }

    const int b0 = blockIdx.x << 7;
    float bS = 0.f, bI = 0.f, bR = 0.f, aS = 0.f, aI = 0.f, aR = 0.f;
    if (t < 128) {
        int gr = b0 + t;
        bS = y0[gr * 3 + 0]; bI = y0[gr * 3 + 1]; bR = y0[gr * 3 + 2];
        yin[t] = bS; yin[128 + t] = bI; yin[256 + t] = bR;
        yin[384 + t] = beta[gr]; yin[512 + t] = gamma_[gr];
        float mx = fmaxf(bS, fmaxf(bI, bR));
        float e0 = __expf(bS - mx), e1 = __expf(bI - mx), e2 = __expf(bR - mx);
        float inv = __fdividef(1.0f, e0 + e1 + e2);
        size_t o = (size_t)gr * 3;
        out[o] = e0 * inv; out[o + 1] = e1 * inv; out[o + 2] = e2 * inv;
    }
    __syncthreads();

    const int wm = w & 3, wn = w >> 2;
    const int m0 = wm << 5;
    const int n2 = wn << 5;
    const int n3 = wn << 4;
    const int lr  = lane & 15;
    const int hi8 = (lane >> 4) << 3;
    const int g   = lane >> 2, tq = lane & 3;

    const u32 a2ro = (u32)((m0 + lr) * SA2 + hi8 * 2);
    const u32 b2ro = (u32)(lr * SW2 + (n2 + hi8) * 2);
    const u32 a3ro = (u32)((m0 + lr) * SA3 + hi8 * 2);
    const u32 b3ro = (u32)(lr * SW3 + (n3 + hi8) * 2);

    const int r1row = t & 127;
    const int cb    = (t >> 7) << 4;

    for (int s = 0; s < T - 1; ++s) {
        float dt = tss[s + 1] - tss[s];
        for (int sub = 0; sub < 4; ++sub) {
            // ---- Layer 1 (fp32) -> split -> A2 h/m ----
            {
                float yv0 = yin[r1row],        yv1 = yin[128 + r1row];
                float yv2 = yin[256 + r1row],  yv3 = yin[384 + r1row];
                float yv4 = yin[512 + r1row];
                int rb = r1row * SA2;
#pragma unroll
                for (int j = 0; j < 16; j += 2) {
                    int c = cb + j;
                    float v0 = b1s[c], v1 = b1s[c + 1];
                    v0 = fmaf(yv0, W1s[c],        v0); v1 = fmaf(yv0, W1s[c + 1],        v1);
                    v0 = fmaf(yv1, W1s[64 + c],   v0); v1 = fmaf(yv1, W1s[64 + c + 1],   v1);
                    v0 = fmaf(yv2, W1s[128 + c],  v0); v1 = fmaf(yv2, W1s[128 + c + 1],  v1);
                    v0 = fmaf(yv3, W1s[192 + c],  v0); v1 = fmaf(yv3, W1s[192 + c + 1],  v1);
                    v0 = fmaf(yv4, W1s[256 + c],  v0); v1 = fmaf(yv4, W1s[256 + c + 1],  v1);
                    u32 hp, mp;
                    split2(tanh_fast(v0), tanh_fast(v1), hp, mp);
                    *(u32*)(smem + SB_A2H + rb + c * 2) = hp;
                    *(u32*)(smem + SB_A2M + rb + c * 2) = mp;
                }
            }
            __syncthreads();

            // ---- L2 GEMM: D2[128][128], K=64, terms hh+mh+hm w/ frag reuse ----
            float acc2[2][4][4];
#pragma unroll
            for (int i = 0; i < 2; ++i)
#pragma unroll
                for (int j = 0; j < 4; ++j)
#pragma unroll
                    for (int c = 0; c < 4; ++c) acc2[i][j][c] = 0.f;
#pragma unroll
            for (int kc = 0; kc < 4; ++kc) {
                u32 ah0[4], ah1[4], am0[4], am1[4], wf0[4], wf1[4];
                ldsm_x4(ah0, sbase + SB_A2H + a2ro + (u32)(kc << 5));
                ldsm_x4(ah1, sbase + SB_A2H + a2ro + (u32)(16 * SA2) + (u32)(kc << 5));
                ldsm_x4(am0, sbase + SB_A2M + a2ro + (u32)(kc << 5));
                ldsm_x4(am1, sbase + SB_A2M + a2ro + (u32)(16 * SA2) + (u32)(kc << 5));
                // Wh: used by hh and mh
                ldsm_x4_t(wf0, sbase + SB_W2H + b2ro + (u32)(kc * 16 * SW2));
                ldsm_x4_t(wf1, sbase + SB_W2H + b2ro + (u32)(kc * 16 * SW2) + 32u);
                mma16816(acc2[0][0], ah0, wf0); mma16816(acc2[0][1], ah0, wf0 + 2);
                mma16816(acc2[0][2], ah0, wf1); mma16816(acc2[0][3], ah0, wf1 + 2);
                mma16816(acc2[1][0], ah1, wf0); mma16816(acc2[1][1], ah1, wf0 + 2);
                mma16816(acc2[1][2], ah1, wf1); mma16816(acc2[1][3], ah1, wf1 + 2);
                mma16816(acc2[0][0], am0, wf0); mma16816(acc2[0][1], am0, wf0 + 2);
                mma16816(acc2[0][2], am0, wf1); mma16816(acc2[0][3], am0, wf1 + 2);
                mma16816(acc2[1][0], am1, wf0); mma16816(acc2[1][1], am1, wf0 + 2);
                mma16816(acc2[1][2], am1, wf1); mma16816(acc2[1][3], am1, wf1 + 2);
                // Wm: used by hm
                ldsm_x4_t(wf0, sbase + SB_W2M + b2ro + (u32)(kc * 16 * SW2));
                ldsm_x4_t(wf1, sbase + SB_W2M + b2ro + (u32)(kc * 16 * SW2) + 32u);
                mma16816(acc2[0][0], ah0, wf0); mma16816(acc2[0][1], ah0, wf0 + 2);
                mma16816(acc2[0][2], ah0, wf1); mma16816(acc2[0][3], ah0, wf1 + 2);
                mma16816(acc2[1][0], ah1, wf0); mma16816(acc2[1][1], ah1, wf0 + 2);
                mma16816(acc2[1][2], ah1, wf1); mma16816(acc2[1][3], ah1, wf1 + 2);
            }
            // ---- epi2: +b2, tanh, split -> A3 h/m ----
#pragma unroll
            for (int mt = 0; mt < 2; ++mt) {
                int rlo = m0 + (mt << 4) + g;
#pragma unroll
                for (int nt = 0; nt < 4; ++nt) {
                    int cc = n2 + (nt << 3) + (tq << 1);
                    float bb0 = b2s[cc], bb1 = b2s[cc + 1];
                    u32 hp, mp;
                    split2(tanh_fast(acc2[mt][nt][0] + bb0),
                           tanh_fast(acc2[mt][nt][1] + bb1), hp, mp);
                    *(u32*)(smem + SB_A3H + rlo * SA3 + cc * 2) = hp;
                    *(u32*)(smem + SB_A3M + rlo * SA3 + cc * 2) = mp;
                    split2(tanh_fast(acc2[mt][nt][2] + bb0),
                           tanh_fast(acc2[mt][nt][3] + bb1), hp, mp);
                    *(u32*)(smem + SB_A3H + (rlo + 8) * SA3 + cc * 2) = hp;
                    *(u32*)(smem + SB_A3M + (rlo + 8) * SA3 + cc * 2) = mp;
                }
            }
            __syncthreads();

            // ---- L3 GEMM: D3[128][64], K=128, frag reuse ----
            float acc3[2][2][4];
#pragma unroll
            for (int i = 0; i < 2; ++i)
#pragma unroll
                for (int j = 0; j < 2; ++j)
#pragma unroll
                    for (int c = 0; c < 4; ++c) acc3[i][j][c] = 0.f;
#pragma unroll
            for (int kc = 0; kc < 8; ++kc) {
                u32 ah0[4], ah1[4], am0[4], am1[4], bf[4];
                ldsm_x4(ah0, sbase + SB_A3H + a3ro + (u32)(kc << 5));
                ldsm_x4(ah1, sbase + SB_A3H + a3ro + (u32)(16 * SA3) + (u32)(kc << 5));
                ldsm_x4(am0, sbase + SB_A3M + a3ro + (u32)(kc << 5));
                ldsm_x4(am1, sbase + SB_A3M + a3ro + (u32)(16 * SA3) + (u32)(kc << 5));
                ldsm_x4_t(bf, sbase + SB_W3H + b3ro + (u32)(kc * 16 * SW3));
                mma16816(acc3[0][0], ah0, bf); mma16816(acc3[0][1], ah0, bf + 2);
                mma16816(acc3[1][0], ah1, bf); mma16816(acc3[1][1], ah1, bf + 2);
                mma16816(acc3[0][0], am0, bf); mma16816(acc3[0][1], am0, bf + 2);
                mma16816(acc3[1][0], am1, bf); mma16816(acc3[1][1], am1, bf + 2);
                ldsm_x4_t(bf, sbase + SB_W3M + b3ro + (u32)(kc * 16 * SW3));
                mma16816(acc3[0][0], ah0, bf); mma16816(acc3[0][1], ah0, bf + 2);
                mma16816(acc3[1][0], ah1, bf); mma16816(acc3[1][1], ah1, bf + 2);
            }
            // ---- epi3: +b3, tanh, W4 partial dot, reduce ----
#pragma unroll
            for (int mt = 0; mt < 2; ++mt) {
#pragma unroll
                for (int p = 0; p < 2; ++p) {
                    int row = m0 + (mt << 4) + g + (p << 3);
                    float s0 = 0.f, s1 = 0.f, s2 = 0.f;
#pragma unroll
                    for (int nt = 0; nt < 2; ++nt) {
                        int cc = n3 + (nt << 3) + (tq << 1);
                        float h0 = tanh_fast(acc3[mt][nt][p ? 2 : 0] + b3s[cc]);
                        float h1 = tanh_fast(acc3[mt][nt][p ? 3 : 1] + b3s[cc + 1]);
                        s0 = fmaf(h0, W4s[cc * 3 + 0], s0); s0 = fmaf(h1, W4s[cc * 3 + 3], s0);
                        s1 = fmaf(h0, W4s[cc * 3 + 1], s1); s1 = fmaf(h1, W4s[cc * 3 + 4], s1);
                        s2 = fmaf(h0, W4s[cc * 3 + 2], s2); s2 = fmaf(h1, W4s[cc * 3 + 5], s2);
                    }
                    s0 += __shfl_xor_sync(0xffffffffu, s0, 1);
                    s1 += __shfl_xor_sync(0xffffffffu, s1, 1);
                    s2 += __shfl_xor_sync(0xffffffffu, s2, 1);
                    s0 += __shfl_xor_sync(0xffffffffu, s0, 2);
                    s1 += __shfl_xor_sync(0xffffffffu, s1, 2);
                    s2 += __shfl_xor_sync(0xffffffffu, s2, 2);
                    if (tq == 0) {
                        red[wn * 384 + row]        = s0;
                        red[wn * 384 + 128 + row]  = s1;
                        red[wn * 384 + 256 + row]  = s2;
                    }
                }
            }
            __syncthreads();

            // ---- RK4 + output ----
            if (t < 128) {
                float s0 = b4s[0] + red[t]        + red[384 + t]
                                  + red[768 + t]  + red[1152 + t];
                float s1 = b4s[1] + red[128 + t]  + red[512 + t]
                                  + red[896 + t]  + red[1280 + t];
                float s2 = b4s[2] + red[256 + t]  + red[640 + t]
                                  + red[1024 + t] + red[1408 + t];
                if (sub == 0)      { aS = s0; aI = s1; aR = s2; }
                else if (sub == 3) { aS += s0; aI += s1; aR += s2; }
                else {
                    aS = fmaf(2.0f, s0, aS); aI = fmaf(2.0f, s1, aI); aR = fmaf(2.0f, s2, aR);
                }
                if (sub < 3) {
                    float cy = (sub == 2) ? dt : 0.5f * dt;
                    yin[t]       = fmaf(cy, s0, bS);
                    yin[128 + t] = fmaf(cy, s1, bI);
                    yin[256 + t] = fmaf(cy, s2, bR);
                } else {
                    float cc = dt * (1.0f / 6.0f);
                    bS = fmaf(cc, aS, bS); bI = fmaf(cc, aI, bI); bR = fmaf(cc, aR, bR);
                    yin[t] = bS; yin[128 + t] = bI; yin[256 + t] = bR;
                    float mx = fmaxf(bS, fmaxf(bI, bR));
                    float e0 = __expf(bS - mx), e1 = __expf(bI - mx), e2 = __expf(bR - mx);
                    float inv = __fdividef(1.0f, e0 + e1 + e2);
                    size_t o = ((size_t)(s + 1) * B + (b0 + t)) * 3;
                    out[o] = e0 * inv; out[o + 1] = e1 * inv; out[o + 2] = e2 * inv;
                }
            }
            __syncthreads();
        }
    }
}

extern "C" void kernel_launch(void* const* d_in, const int* in_sizes, int n_in,
                              void* d_out, int out_size) {
    const float* y0 = (const float*)d_in[0];
    const float* ts = (const float*)d_in[1];
    const float* be = (const float*)d_in[2];
    const float* ga = (const float*)d_in[3];
    const float* W1 = (const float*)d_in[4];
    const float* b1 = (const float*)d_in[5];
    const float* W2 = (const float*)d_in[6];
    const float* b2 = (const float*)d_in[7];
    const float* W3 = (const float*)d_in[8];
    const float* b3 = (const float*)d_in[9];
    const float* W4 = (const float*)d_in[10];
    const float* b4 = (const float*)d_in[11];

    int B = in_sizes[2];
    int T = in_sizes[1];

    cudaFuncSetAttribute(node_sir_mma, cudaFuncAttributeMaxDynamicSharedMemorySize, SB_TOTAL);
    node_sir_mma<<<B / 128, 512, SB_TOTAL>>>(
        y0, ts, be, ga, W1, b1, W2, b2, W3, b3, W4, b4, (float*)d_out, B, T);
}